// round 1
// baseline (speedup 1.0000x reference)
#include <cuda_runtime.h>
#include <cuda_bf16.h>
#include <cstdint>

// Problem constants
#define BATCH   2048
#define SEQ     28
#define DMODEL  1024
#define NHEAD   16
#define DHEAD   64
#define RROWS   (BATCH * SEQ)          // 57344
#define RC      (RROWS * DMODEL)       // 58,720,256 elements

// Scratch (device globals: allocation-free rule)
__device__ float g_h  [RC];
__device__ float g_q  [RC];
__device__ float g_k  [RC];
__device__ float g_v  [RC];
__device__ float g_ctx[RC];

// ---------------------------------------------------------------------------
// LayerNorm: one block per row of 1024
// ---------------------------------------------------------------------------
__global__ __launch_bounds__(256) void ln_kernel(const float* __restrict__ x,
                                                 const float* __restrict__ gamma,
                                                 const float* __restrict__ beta)
{
    int row = blockIdx.x;
    int tid = threadIdx.x;
    const float4* xr = (const float4*)(x + (size_t)row * DMODEL);
    float4 v = xr[tid];

    float s = v.x + v.y + v.z + v.w;
    float q = v.x * v.x + v.y * v.y + v.z * v.z + v.w * v.w;
    #pragma unroll
    for (int o = 16; o; o >>= 1) {
        s += __shfl_xor_sync(0xffffffffu, s, o);
        q += __shfl_xor_sync(0xffffffffu, q, o);
    }
    __shared__ float ss[8], sq[8];
    int wid = tid >> 5, lane = tid & 31;
    if (lane == 0) { ss[wid] = s; sq[wid] = q; }
    __syncthreads();
    __shared__ float s_mean, s_rstd;
    if (tid == 0) {
        float S = 0.f, Q = 0.f;
        #pragma unroll
        for (int i = 0; i < 8; ++i) { S += ss[i]; Q += sq[i]; }
        float mean = S * (1.0f / DMODEL);
        float var  = Q * (1.0f / DMODEL) - mean * mean;
        s_mean = mean;
        s_rstd = rsqrtf(var + 1e-5f);
    }
    __syncthreads();
    float mean = s_mean, rstd = s_rstd;

    float4 gv = ((const float4*)gamma)[tid];
    float4 bv = ((const float4*)beta)[tid];
    float4 o;
    o.x = (v.x - mean) * rstd * gv.x + bv.x;
    o.y = (v.y - mean) * rstd * gv.y + bv.y;
    o.z = (v.z - mean) * rstd * gv.z + bv.z;
    o.w = (v.w - mean) * rstd * gv.w + bv.w;
    ((float4*)(g_h + (size_t)row * DMODEL))[tid] = o;
}

// ---------------------------------------------------------------------------
// TF32 GEMM: C[57344 x 1024] = A[57344 x 1024] * B[1024 x 1024] (+ resid)
// Tile 128x128x32, 256 threads (8 warps as 2x4), mma.sync m16n8k8 tf32.
// ---------------------------------------------------------------------------
#define BM 128
#define BN 128
#define BK 32
#define ASTR (BM + 1)   // 129: makes A transpose-stores + frag loads workable
#define BSTR (BN + 4)   // 132: keeps float4-aligned, conflict-free stores

__device__ __forceinline__ unsigned f2tf(float x)
{
    unsigned u;
    asm("cvt.rna.tf32.f32 %0, %1;" : "=r"(u) : "f"(x));
    return u;
}

__device__ __forceinline__ void mma_tf32(float c[4],
                                         unsigned a0, unsigned a1, unsigned a2, unsigned a3,
                                         unsigned b0, unsigned b1)
{
    asm volatile(
        "mma.sync.aligned.m16n8k8.row.col.f32.tf32.tf32.f32 "
        "{%0,%1,%2,%3}, {%4,%5,%6,%7}, {%8,%9}, {%0,%1,%2,%3};"
        : "+f"(c[0]), "+f"(c[1]), "+f"(c[2]), "+f"(c[3])
        : "r"(a0), "r"(a1), "r"(a2), "r"(a3), "r"(b0), "r"(b1));
}

__device__ __forceinline__ void gemm_body(const float* __restrict__ A,
                                          const float* __restrict__ B,
                                          float* __restrict__ C,
                                          const float* __restrict__ resid,
                                          int mt, int nt)
{
    __shared__ unsigned As[BK][ASTR];
    __shared__ unsigned Bs[BK][BSTR];

    const int tid  = threadIdx.x;
    const int wid  = tid >> 5;
    const int lane = tid & 31;
    const int g    = lane >> 2;   // 0..7
    const int r    = lane & 3;    // 0..3
    const int wm   = (wid & 1) * 64;
    const int wn   = (wid >> 1) * 32;

    const int gm = mt * BM;
    const int gn = nt * BN;

    // global-load mappings
    const int a_m = tid >> 3;         // 0..31
    const int a_k = (tid & 7) * 4;    // 0..28
    const int b_k = tid >> 5;         // 0..7
    const int b_n = (tid & 31) * 4;   // 0..124

    float4 pa[4], pb[4];
    {
        const float* Ap = A + (size_t)(gm + a_m) * DMODEL + a_k;
        #pragma unroll
        for (int it = 0; it < 4; ++it)
            pa[it] = *(const float4*)(Ap + (size_t)(32 * it) * DMODEL);
        const float* Bp = B + (size_t)b_k * DMODEL + gn + b_n;
        #pragma unroll
        for (int it = 0; it < 4; ++it)
            pb[it] = *(const float4*)(Bp + (size_t)(8 * it) * DMODEL);
    }

    float acc[4][4][4];
    #pragma unroll
    for (int i = 0; i < 4; ++i)
        #pragma unroll
        for (int j = 0; j < 4; ++j)
            #pragma unroll
            for (int t = 0; t < 4; ++t) acc[i][j][t] = 0.f;

    const int KT = DMODEL / BK;   // 32
    for (int kt = 0; kt < KT; ++kt) {
        // stage current tile into smem (tf32-rounded)
        #pragma unroll
        for (int it = 0; it < 4; ++it) {
            As[a_k + 0][a_m + 32 * it] = f2tf(pa[it].x);
            As[a_k + 1][a_m + 32 * it] = f2tf(pa[it].y);
            As[a_k + 2][a_m + 32 * it] = f2tf(pa[it].z);
            As[a_k + 3][a_m + 32 * it] = f2tf(pa[it].w);
            uint4 tb;
            tb.x = f2tf(pb[it].x); tb.y = f2tf(pb[it].y);
            tb.z = f2tf(pb[it].z); tb.w = f2tf(pb[it].w);
            *(uint4*)&Bs[b_k + 8 * it][b_n] = tb;
        }
        __syncthreads();

        // prefetch next tile
        if (kt < KT - 1) {
            const float* Ap = A + (size_t)(gm + a_m) * DMODEL + (kt + 1) * BK + a_k;
            #pragma unroll
            for (int it = 0; it < 4; ++it)
                pa[it] = *(const float4*)(Ap + (size_t)(32 * it) * DMODEL);
            const float* Bp = B + (size_t)((kt + 1) * BK + b_k) * DMODEL + gn + b_n;
            #pragma unroll
            for (int it = 0; it < 4; ++it)
                pb[it] = *(const float4*)(Bp + (size_t)(8 * it) * DMODEL);
        }

        // compute
        #pragma unroll
        for (int ks = 0; ks < 4; ++ks) {
            const int k0 = ks * 8;
            unsigned af[4][4], bf[4][2];
            #pragma unroll
            for (int i = 0; i < 4; ++i) {
                const int m = wm + 16 * i + g;
                af[i][0] = As[k0 + r][m];
                af[i][1] = As[k0 + r][m + 8];
                af[i][2] = As[k0 + r + 4][m];
                af[i][3] = As[k0 + r + 4][m + 8];
            }
            #pragma unroll
            for (int j = 0; j < 4; ++j) {
                const int n = wn + 8 * j + g;
                bf[j][0] = Bs[k0 + r][n];
                bf[j][1] = Bs[k0 + r + 4][n];
            }
            #pragma unroll
            for (int i = 0; i < 4; ++i)
                #pragma unroll
                for (int j = 0; j < 4; ++j)
                    mma_tf32(acc[i][j], af[i][0], af[i][1], af[i][2], af[i][3],
                             bf[j][0], bf[j][1]);
        }
        __syncthreads();
    }

    // epilogue
    #pragma unroll
    for (int i = 0; i < 4; ++i) {
        #pragma unroll
        for (int j = 0; j < 4; ++j) {
            const int row = gm + wm + 16 * i + g;
            const int col = gn + wn + 8 * j + 2 * r;
            float2 v0 = make_float2(acc[i][j][0], acc[i][j][1]);
            float2 v1 = make_float2(acc[i][j][2], acc[i][j][3]);
            if (resid) {
                float2 r0 = *(const float2*)&resid[(size_t)row * DMODEL + col];
                float2 r1 = *(const float2*)&resid[(size_t)(row + 8) * DMODEL + col];
                v0.x += r0.x; v0.y += r0.y;
                v1.x += r1.x; v1.y += r1.y;
            }
            *(float2*)&C[(size_t)row * DMODEL + col]       = v0;
            *(float2*)&C[(size_t)(row + 8) * DMODEL + col] = v1;
        }
    }
}

__global__ __launch_bounds__(256) void gemm_qkv_kernel(const float* __restrict__ wq,
                                                       const float* __restrict__ wk,
                                                       const float* __restrict__ wv)
{
    const int mat = blockIdx.x >> 3;
    const float* B = (mat == 0) ? wq : (mat == 1) ? wk : wv;
    float* C = (mat == 0) ? g_q : (mat == 1) ? g_k : g_v;
    gemm_body(g_h, B, C, nullptr, blockIdx.y, blockIdx.x & 7);
}

__global__ __launch_bounds__(256) void gemm_out_kernel(const float* __restrict__ wo,
                                                       float* __restrict__ out)
{
    gemm_body(g_ctx, wo, out, g_h, blockIdx.y, blockIdx.x);
}

// ---------------------------------------------------------------------------
// Attention: one block per (b, h). scores 28x28 + teeth bias, softmax, ctx.
// ---------------------------------------------------------------------------
__global__ __launch_bounds__(256) void attn_kernel()
{
    const int h = blockIdx.x;
    const int b = blockIdx.y;
    __shared__ float sq[SEQ][65], sk[SEQ][65], sv[SEQ][65];
    __shared__ float sp[SEQ][29];

    const int tid = threadIdx.x;
    const size_t base = (size_t)b * SEQ * DMODEL + (size_t)h * DHEAD;

    for (int idx = tid; idx < SEQ * (DHEAD / 4); idx += 256) {
        const int row = idx >> 4;            // 0..27
        const int c   = (idx & 15) * 4;      // 0..60
        const size_t gofs = base + (size_t)row * DMODEL + c;
        float4 qv = *(const float4*)(g_q + gofs);
        float4 kv = *(const float4*)(g_k + gofs);
        float4 vv = *(const float4*)(g_v + gofs);
        sq[row][c] = qv.x; sq[row][c + 1] = qv.y; sq[row][c + 2] = qv.z; sq[row][c + 3] = qv.w;
        sk[row][c] = kv.x; sk[row][c + 1] = kv.y; sk[row][c + 2] = kv.z; sk[row][c + 3] = kv.w;
        sv[row][c] = vv.x; sv[row][c + 1] = vv.y; sv[row][c + 2] = vv.z; sv[row][c + 3] = vv.w;
    }
    __syncthreads();

    const float slope = exp2f(-0.5f * (float)(h + 1));

    for (int e = tid; e < SEQ * SEQ; e += 256) {
        const int i = e / SEQ;
        const int j = e - i * SEQ;
        float acc = 0.f;
        #pragma unroll
        for (int d = 0; d < DHEAD; ++d) acc += sq[i][d] * sk[j][d];
        int dc = (i % 14) - (j % 14); if (dc < 0) dc = -dc;
        int dr = (i / 14) - (j / 14); if (dr < 0) dr = -dr;
        sp[i][j] = acc + slope * (float)(dc + dr);
    }
    __syncthreads();

    if (tid < SEQ) {
        float m = -1e30f;
        #pragma unroll
        for (int j = 0; j < SEQ; ++j) m = fmaxf(m, sp[tid][j]);
        float s = 0.f;
        #pragma unroll
        for (int j = 0; j < SEQ; ++j) s += __expf(sp[tid][j] - m);
        const float inv = 1.0f / s;
        #pragma unroll
        for (int j = 0; j < SEQ; ++j) sp[tid][j] = __expf(sp[tid][j] - m) * inv;
    }
    __syncthreads();

    for (int e = tid; e < SEQ * DHEAD; e += 256) {
        const int i = e >> 6;
        const int d = e & 63;
        float acc = 0.f;
        #pragma unroll
        for (int j = 0; j < SEQ; ++j) acc += sp[i][j] * sv[j][d];
        g_ctx[base + (size_t)i * DMODEL + d] = acc;
    }
}

// ---------------------------------------------------------------------------
// Launch
// ---------------------------------------------------------------------------
extern "C" void kernel_launch(void* const* d_in, const int* in_sizes, int n_in,
                              void* d_out, int out_size)
{
    const float* hidden = (const float*)d_in[0];
    const float* wq     = (const float*)d_in[1];
    const float* wk     = (const float*)d_in[2];
    const float* wv     = (const float*)d_in[3];
    const float* wo     = (const float*)d_in[4];
    const float* gamma  = (const float*)d_in[5];
    const float* beta   = (const float*)d_in[6];
    float* out = (float*)d_out;

    ln_kernel<<<RROWS, 256>>>(hidden, gamma, beta);
    gemm_qkv_kernel<<<dim3(24, RROWS / BM), 256>>>(wq, wk, wv);
    attn_kernel<<<dim3(NHEAD, BATCH), 256>>>();
    gemm_out_kernel<<<dim3(8, RROWS / BM), 256>>>(wo, out);
}